// round 15
// baseline (speedup 1.0000x reference)
#include <cuda_runtime.h>
#include <cuda_fp16.h>
#include <cstdint>

#define B_   8
#define T_   1024
#define C_   768
#define H_   12
#define D_   64
#define C3_  2304
#define MT_  (B_ * T_)      // 8192 rows
#define TQ_  (T_ / 64)      // 16 q-tiles
#define QSC_ 0.18033688011112042f   // 0.125 * log2(e)

__device__ __half g_qkv_h[(size_t)MT_ * C3_];  // [t][3C]; q pre-scaled by QSC_
__device__ __half g_att_h[(size_t)MT_ * C_];   // [t][C]
__device__ __half g_xh  [(size_t)MT_ * C_];    // x as fp16
__device__ __half g_waT [(size_t)C3_ * C_];    // w_attn^T  [N][K]
__device__ __half g_wpT [(size_t)C_  * C_];    // w_proj^T  [N][K]

// ---------------------------------------------------------------------------
__device__ __forceinline__ unsigned f2h2(float x, float y) {
    __half2 h = __floats2half2_rn(x, y);
    return *reinterpret_cast<unsigned*>(&h);
}
__device__ __forceinline__ uint32_t s2u(const void* p) {
    return (uint32_t)__cvta_generic_to_shared(p);
}
__device__ __forceinline__ void mma_f16(float c[4],
    unsigned a0, unsigned a1, unsigned a2, unsigned a3,
    unsigned b0, unsigned b1)
{
    asm volatile(
        "mma.sync.aligned.m16n8k16.row.col.f32.f16.f16.f32 "
        "{%0,%1,%2,%3}, {%4,%5,%6,%7}, {%8,%9}, {%0,%1,%2,%3};\n"
        : "+f"(c[0]), "+f"(c[1]), "+f"(c[2]), "+f"(c[3])
        : "r"(a0), "r"(a1), "r"(a2), "r"(a3), "r"(b0), "r"(b1));
}
__device__ __forceinline__ void ldsm_x4(unsigned& d0, unsigned& d1,
                                        unsigned& d2, unsigned& d3, unsigned saddr)
{
    asm volatile("ldmatrix.sync.aligned.m8n8.x4.shared.b16 {%0,%1,%2,%3}, [%4];\n"
                 : "=r"(d0), "=r"(d1), "=r"(d2), "=r"(d3) : "r"(saddr));
}
__device__ __forceinline__ void ldsm_x4_t(unsigned& d0, unsigned& d1,
                                          unsigned& d2, unsigned& d3, unsigned saddr)
{
    asm volatile("ldmatrix.sync.aligned.m8n8.x4.trans.shared.b16 {%0,%1,%2,%3}, [%4];\n"
                 : "=r"(d0), "=r"(d1), "=r"(d2), "=r"(d3) : "r"(saddr));
}
__device__ __forceinline__ void cp16(uint32_t saddr, const void* gaddr) {
    asm volatile("cp.async.cg.shared.global [%0], [%1], 16;"
                 :: "r"(saddr), "l"(gaddr));
}
#define CP_COMMIT()  asm volatile("cp.async.commit_group;" ::: "memory")
#define CP_WAIT0()   asm volatile("cp.async.wait_group 0;" ::: "memory")
#define CP_WAIT1()   asm volatile("cp.async.wait_group 1;" ::: "memory")

// ---------------------------------------------------------------------------
// prep kernels
// ---------------------------------------------------------------------------
__global__ void cvt_x_kernel(const float* __restrict__ x, __half* __restrict__ xh,
                             int n4) {
    int i = blockIdx.x * blockDim.x + threadIdx.x;
    if (i < n4) {
        float4 v = ((const float4*)x)[i];
        uint2 h;
        h.x = f2h2(v.x, v.y);
        h.y = f2h2(v.z, v.w);
        ((uint2*)xh)[i] = h;
    }
}

// z=0: w_attn (N=2304) -> waT ; z=1: w_proj (N=768) -> wpT
__global__ __launch_bounds__(256) void transpose_cvt2_kernel(
    const float* __restrict__ wa, __half* __restrict__ waT,
    const float* __restrict__ wp, __half* __restrict__ wpT)
{
    const float* w;  __half* wt;  int N;
    if (blockIdx.z == 0) { w = wa; wt = waT; N = C3_; }
    else                 { w = wp; wt = wpT; N = C_;  }
    int n0 = blockIdx.x * 32, k0 = blockIdx.y * 32;
    if (n0 >= N) return;
    __shared__ float tile[32][33];
    int tx = threadIdx.x & 31, ty = threadIdx.x >> 5;
    #pragma unroll
    for (int i = ty; i < 32; i += 8)
        tile[i][tx] = w[(size_t)(k0 + i) * N + n0 + tx];
    __syncthreads();
    #pragma unroll
    for (int i = ty; i < 32; i += 8)
        wt[(size_t)(n0 + i) * C_ + k0 + tx] = __float2half(tile[tx][i]);
}

// ---------------------------------------------------------------------------
// FP16 GEMM 128x128: BK=64, 3-stage cp.async ring, 96 KB dyn smem.
// HALF_OUT epilogue pre-scales q columns (col < 768) by QSC_ in fp32.
// ---------------------------------------------------------------------------
#define STAGEB 32768u

template<bool HALF_OUT>
__global__ __launch_bounds__(256, 2) void gemm_f16d(
    const __half* __restrict__ A, const __half* __restrict__ Bt,
    const float* __restrict__ bias, void* __restrict__ Cout,
    int M, int N, int K)
{
    extern __shared__ __align__(128) char dsm[];

    const int tid  = threadIdx.x;
    const int lane = tid & 31;
    const int wid  = tid >> 5;
    const int wm   = wid >> 2;
    const int wn   = wid & 3;
    const int g    = lane >> 2;
    const int t4   = lane & 3;
    const int l7   = lane & 7;
    const int lb8  = (lane >> 3) & 1;
    const int lb16 = (lane >> 4) & 1;

    const int rowBase = blockIdx.y * 128;
    const int colBase = blockIdx.x * 128;

    const unsigned Sb = s2u(dsm);

    float acc[4][4][4];
    #pragma unroll
    for (int i = 0; i < 4; i++)
        #pragma unroll
        for (int j = 0; j < 4; j++)
            #pragma unroll
            for (int q = 0; q < 4; q++) acc[i][j][q] = 0.f;

    const int ldR = tid >> 1;
    const int cb  = (tid & 1) * 4;
    unsigned soff[4];
    #pragma unroll
    for (int j = 0; j < 4; j++)
        soff[j] = (unsigned)(ldR * 128 + (((cb + j) ^ (ldR & 7)) << 4));
    const __half* gA = A  + (size_t)(rowBase + ldR) * K + (tid & 1) * 32;
    const __half* gB = Bt + (size_t)(colBase + ldR) * K + (tid & 1) * 32;

    #define ISSUE(s, wb) {                                        \
        const unsigned bo = (unsigned)(wb) * STAGEB;              \
        const __half* ga = gA + (size_t)(s) * 64;                 \
        const __half* gb = gB + (size_t)(s) * 64;                 \
        cp16(Sb + bo + soff[0], ga);                              \
        cp16(Sb + bo + soff[1], ga + 8);                          \
        cp16(Sb + bo + soff[2], ga + 16);                         \
        cp16(Sb + bo + soff[3], ga + 24);                         \
        cp16(Sb + bo + 16384u + soff[0], gb);                     \
        cp16(Sb + bo + 16384u + soff[1], gb + 8);                 \
        cp16(Sb + bo + 16384u + soff[2], gb + 16);                \
        cp16(Sb + bo + 16384u + soff[3], gb + 24);                \
        CP_COMMIT();                                              \
    }

    const int NS = K / 64;
    ISSUE(0, 0);
    ISSUE(1, 1);
    int wbuf = 2, rbuf = 0;

    const unsigned aRow = (unsigned)((wm * 64 + l7 + 8 * lb8) * 128);
    const unsigned bRow = (unsigned)((l7 + 8 * lb16) * 128) + 16384u;

    for (int s = 0; s < NS; s++) {
        if (s + 1 < NS) CP_WAIT1(); else CP_WAIT0();
        __syncthreads();
        if (s + 2 < NS) {
            ISSUE(s + 2, wbuf);
            wbuf = (wbuf == 2) ? 0 : wbuf + 1;
        }

        const unsigned base = Sb + (unsigned)rbuf * STAGEB;
        const unsigned aw = base + aRow;
        const unsigned bw = base + bRow;
        #pragma unroll
        for (int kb = 0; kb < 4; kb++) {
            const unsigned ach = (unsigned)(((kb * 2 + lb16) ^ l7) << 4);
            const unsigned bch = (unsigned)(((kb * 2 + lb8)  ^ l7) << 4);
            unsigned af[4][4];
            #pragma unroll
            for (int mt = 0; mt < 4; mt++)
                ldsm_x4(af[mt][0], af[mt][1], af[mt][2], af[mt][3],
                        aw + (unsigned)(mt * 2048) + ach);
            unsigned bf[4][2];
            #pragma unroll
            for (int ntp = 0; ntp < 2; ntp++) {
                unsigned d0, d1, d2, d3;
                ldsm_x4(d0, d1, d2, d3,
                        bw + (unsigned)((wn * 32 + ntp * 16) * 128) + bch);
                bf[ntp * 2 + 0][0] = d0; bf[ntp * 2 + 0][1] = d1;
                bf[ntp * 2 + 1][0] = d2; bf[ntp * 2 + 1][1] = d3;
            }
            #pragma unroll
            for (int mt = 0; mt < 4; mt++)
                #pragma unroll
                for (int nt = 0; nt < 4; nt++)
                    mma_f16(acc[mt][nt], af[mt][0], af[mt][1], af[mt][2], af[mt][3],
                            bf[nt][0], bf[nt][1]);
        }
        rbuf = (rbuf == 2) ? 0 : rbuf + 1;
    }
    #undef ISSUE

    #pragma unroll
    for (int mt = 0; mt < 4; mt++) {
        #pragma unroll
        for (int nt = 0; nt < 4; nt++) {
            int r0 = rowBase + wm * 64 + mt * 16 + g;
            int c  = colBase + wn * 32 + nt * 8 + 2 * t4;
            float bx = bias[c], by = bias[c + 1];
            if (HALF_OUT) {
                float sc = (c < C_) ? QSC_ : 1.0f;   // pre-scale q columns
                __half* out = (__half*)Cout;
                *(unsigned*)(out + (size_t)r0 * N + c) =
                    f2h2((acc[mt][nt][0] + bx) * sc, (acc[mt][nt][1] + by) * sc);
                *(unsigned*)(out + (size_t)(r0 + 8) * N + c) =
                    f2h2((acc[mt][nt][2] + bx) * sc, (acc[mt][nt][3] + by) * sc);
            } else {
                float* out = (float*)Cout;
                *(float2*)(out + (size_t)r0 * N + c) =
                    make_float2(acc[mt][nt][0] + bx, acc[mt][nt][1] + by);
                *(float2*)(out + (size_t)(r0 + 8) * N + c) =
                    make_float2(acc[mt][nt][2] + bx, acc[mt][nt][3] + by);
            }
        }
    }
}

// ---------------------------------------------------------------------------
// Flash causal attention, paired q-tiles: 256 threads, 8 warps.
// Warps 0-3 own q-tile 2p, warps 4-7 own q-tile 2p+1; K/V tiles loaded ONCE
// and consumed by both halves (KV traffic halved). exp2-domain softmax,
// q pre-scaled by 0.125*log2e. Inner body identical to R14.
// ---------------------------------------------------------------------------
#define QST2 72
#define KST2 72
#define PST2 40

__global__ __launch_bounds__(256) void attn_f16q2(
    const __half* __restrict__ qkv, __half* __restrict__ outp)
{
    __shared__ __align__(16) __half Qs[128 * QST2];
    __shared__ __align__(16) __half Ks[2][32 * KST2];
    __shared__ __align__(16) __half Vs[2][32 * KST2];
    __shared__ __align__(16) __half Ps[128 * PST2];
    const unsigned KVB = 32 * KST2 * 2;

    const int tid  = threadIdx.x;
    const int lane = tid & 31;
    const int wid  = tid >> 5;            // 0..7
    const int wg   = wid >> 2;            // 0: tile 2p, 1: tile 2p+1
    const int g    = lane >> 2;
    const int t4   = lane & 3;

    const int bh = blockIdx.y;
    const int b  = bh / H_;
    const int h  = bh % H_;
    const int p  = blockIdx.x;            // 0..TQ_/2-1
    const int qt = 2 * p + wg;            // this warp's q-tile
    const int qBase0 = 2 * p * 64;        // block's 128-row base

    const __half* qptr = qkv + (size_t)b * T_ * C3_ + h * D_;
    const __half* kptr = qptr + C_;
    const __half* vptr = qptr + 2 * C_;

    const unsigned qoff = ((lane & 7) + ((lane >> 3) & 1) * 8) * QST2
                        + ((lane >> 4) & 1) * 8;
    const unsigned koff = ((lane & 7) + ((lane >> 4) & 1) * 8) * KST2
                        + ((lane >> 3) & 1) * 8;
    const unsigned voff = ((lane & 7) + ((lane >> 3) & 1) * 8) * KST2
                        + ((lane >> 4) & 1) * 8;
    const unsigned poff = ((lane & 7) + ((lane >> 3) & 1) * 8) * PST2
                        + ((lane >> 4) & 1) * 8;
    const unsigned Qs_base = s2u(&Qs[0]);
    const unsigned Ks_base = s2u(&Ks[0][0]);
    const unsigned Vs_base = s2u(&Vs[0][0]);
    const unsigned Ps_base = s2u(&Ps[0]);

    // KV loader: 256 threads -> one 16B chunk per K and V tile each
    const int r0l = tid >> 3;             // 0..31
    const int c8l = (tid & 7) << 3;
    const unsigned sK0 = Ks_base + (unsigned)(r0l * KST2 + c8l) * 2;
    const unsigned sV0 = Vs_base + (unsigned)(r0l * KST2 + c8l) * 2;

    #define AISSUE(kt, wb) {                                                  \
        const unsigned bo = (unsigned)(wb) * KVB;                             \
        cp16(sK0 + bo, kptr + (size_t)((kt) * 32 + r0l) * C3_ + c8l);         \
        cp16(sV0 + bo, vptr + (size_t)((kt) * 32 + r0l) * C3_ + c8l);         \
        CP_COMMIT();                                                          \
    }

    // stage 128-row Q region
    #pragma unroll
    for (int l = 0; l < 4; l++) {
        int idx = tid + l * 256;
        int r = idx >> 3, c8 = (idx & 7) << 3;
        *(uint4*)&Qs[r * QST2 + c8] =
            *(const uint4*)(qptr + (size_t)(qBase0 + r) * C3_ + c8);
    }
    AISSUE(0, 0);
    __syncthreads();

    unsigned qa[4][4];
    #pragma unroll
    for (int kq = 0; kq < 4; kq++)
        ldsm_x4(qa[kq][0], qa[kq][1], qa[kq][2], qa[kq][3],
                Qs_base + (qoff + (unsigned)(wid * 16 * QST2 + kq * 16)) * 2);

    float o[8][4];
    #pragma unroll
    for (int nt = 0; nt < 8; nt++)
        #pragma unroll
        for (int q = 0; q < 4; q++) o[nt][q] = 0.f;
    float m0 = -1e30f, m1 = -1e30f, l0 = 0.f, l1 = 0.f;

    const int rowL = wid * 16 + g;        // 0..127 within Q region
    const int row0 = qBase0 + rowL;
    const int row1 = row0 + 8;

    const int myktmax = 2 * qt + 1;       // this warp's last key tile
    const int gktmax  = 4 * p + 3;        // block's last key tile
    for (int kt = 0; kt <= gktmax; kt++) {
        const unsigned rb = (unsigned)(kt & 1) * KVB;

        CP_WAIT0();
        __syncthreads();
        if (kt + 1 <= gktmax) AISSUE(kt + 1, (kt + 1) & 1);

        if (kt <= myktmax) {
            const int kBase = kt * 32;
            const bool domask = (kt >= 2 * qt);

            float s[4][4];
            #pragma unroll
            for (int nt = 0; nt < 4; nt++)
                #pragma unroll
                for (int q = 0; q < 4; q++) s[nt][q] = 0.f;

            #pragma unroll
            for (int kq = 0; kq < 4; kq++) {
                #pragma unroll
                for (int ntp = 0; ntp < 2; ntp++) {
                    unsigned d0, d1, d2, d3;
                    ldsm_x4(d0, d1, d2, d3,
                            Ks_base + rb +
                            (koff + (unsigned)(ntp * 16 * KST2 + kq * 16)) * 2);
                    mma_f16(s[ntp * 2 + 0], qa[kq][0], qa[kq][1], qa[kq][2],
                            qa[kq][3], d0, d1);
                    mma_f16(s[ntp * 2 + 1], qa[kq][0], qa[kq][1], qa[kq][2],
                            qa[kq][3], d2, d3);
                }
            }

            if (domask) {
                #pragma unroll
                for (int nt = 0; nt < 4; nt++) {
                    #pragma unroll
                    for (int q = 0; q < 4; q++) {
                        int col = kBase + nt * 8 + 2 * t4 + (q & 1);
                        int row = (q < 2) ? row0 : row1;
                        if (col > row) s[nt][q] = -1e30f;
                    }
                }
            }

            float mt0 = -1e30f, mt1 = -1e30f;
            #pragma unroll
            for (int nt = 0; nt < 4; nt++) {
                mt0 = fmaxf(mt0, fmaxf(s[nt][0], s[nt][1]));
                mt1 = fmaxf(mt1, fmaxf(s[nt][2], s[nt][3]));
            }
            mt0 = fmaxf(mt0, __shfl_xor_sync(0xffffffffu, mt0, 1));
            mt0 = fmaxf(mt0, __shfl_xor_sync(0xffffffffu, mt0, 2));
            mt1 = fmaxf(mt1, __shfl_xor_sync(0xffffffffu, mt1, 1));
            mt1 = fmaxf(mt1, __shfl_xor_sync(0xffffffffu, mt1, 2));

            float mn0 = fmaxf(m0, mt0), mn1 = fmaxf(m1, mt1);
            float al0 = exp2f(m0 - mn0), al1 = exp2f(m1 - mn1);
            m0 = mn0; m1 = mn1;

            float rs0 = 0.f, rs1 = 0.f;
            #pragma unroll
            for (int nt = 0; nt < 4; nt++) {
                s[nt][0] = exp2f(s[nt][0] - mn0);
                s[nt][1] = exp2f(s[nt][1] - mn0);
                s[nt][2] = exp2f(s[nt][2] - mn1);
                s[nt][3] = exp2f(s[nt][3] - mn1);
                rs0 += s[nt][0] + s[nt][1];
                rs1 += s[nt][2] + s[nt][3];
            }
            rs0 += __shfl_xor_sync(0xffffffffu, rs0, 1);
            rs0 += __shfl_xor_sync(0xffffffffu, rs0, 2);
            rs1 += __shfl_xor_sync(0xffffffffu, rs1, 1);
            rs1 += __shfl_xor_sync(0xffffffffu, rs1, 2);
            l0 = l0 * al0 + rs0;
            l1 = l1 * al1 + rs1;

            #pragma unroll
            for (int nt = 0; nt < 8; nt++) {
                o[nt][0] *= al0; o[nt][1] *= al0;
                o[nt][2] *= al1; o[nt][3] *= al1;
            }

            #pragma unroll
            for (int nt = 0; nt < 4; nt++) {
                int c = nt * 8 + 2 * t4;
                *(unsigned*)&Ps[(rowL    ) * PST2 + c] = f2h2(s[nt][0], s[nt][1]);
                *(unsigned*)&Ps[(rowL + 8) * PST2 + c] = f2h2(s[nt][2], s[nt][3]);
            }
            __syncwarp();

            #pragma unroll
            for (int kb = 0; kb < 2; kb++) {
                unsigned a0, a1, a2, a3;
                ldsm_x4(a0, a1, a2, a3,
                        Ps_base + (poff + (unsigned)(wid * 16 * PST2 + kb * 16)) * 2);
                #pragma unroll
                for (int ntp = 0; ntp < 4; ntp++) {
                    unsigned d0, d1, d2, d3;
                    ldsm_x4_t(d0, d1, d2, d3,
                              Vs_base + rb +
                              (voff + (unsigned)(kb * 16 * KST2 + ntp * 16)) * 2);
                    mma_f16(o[ntp * 2 + 0], a0, a1, a2, a3, d0, d1);
                    mma_f16(o[ntp * 2 + 1], a0, a1, a2, a3, d2, d3);
                }
            }
        }
    }
    #undef AISSUE

    float inv0 = 1.f / l0, inv1 = 1.f / l1;
    #pragma unroll
    for (int nt = 0; nt < 8; nt++) {
        int d = nt * 8 + 2 * t4;
        unsigned u0 = f2h2(o[nt][0] * inv0, o[nt][1] * inv0);
        unsigned u1 = f2h2(o[nt][2] * inv1, o[nt][3] * inv1);
        *(unsigned*)(outp + ((size_t)b * T_ + row0) * C_ + h * D_ + d) = u0;
        *(unsigned*)(outp + ((size_t)b * T_ + row1) * C_ + h * D_ + d) = u1;
    }
}

// ---------------------------------------------------------------------------
extern "C" void kernel_launch(void* const* d_in, const int* in_sizes, int n_in,
                              void* d_out, int out_size)
{
    (void)in_sizes; (void)n_in; (void)out_size;
    const float* x      = (const float*)d_in[0];
    const float* w_attn = (const float*)d_in[1];
    const float* b_attn = (const float*)d_in[2];
    const float* w_proj = (const float*)d_in[3];
    const float* b_proj = (const float*)d_in[4];
    float* out = (float*)d_out;

    __half *qkv_h, *att_h, *xh, *waT, *wpT;
    cudaGetSymbolAddress((void**)&qkv_h, g_qkv_h);
    cudaGetSymbolAddress((void**)&att_h, g_att_h);
    cudaGetSymbolAddress((void**)&xh,    g_xh);
    cudaGetSymbolAddress((void**)&waT,   g_waT);
    cudaGetSymbolAddress((void**)&wpT,   g_wpT);

    cudaFuncSetAttribute(gemm_f16d<true>,
                         cudaFuncAttributeMaxDynamicSharedMemorySize, 98304);
    cudaFuncSetAttribute(gemm_f16d<false>,
                         cudaFuncAttributeMaxDynamicSharedMemorySize, 98304);

    const int n4 = MT_ * C_ / 4;
    cvt_x_kernel<<<(n4 + 255) / 256, 256>>>(x, xh, n4);
    transpose_cvt2_kernel<<<dim3(C3_ / 32, C_ / 32, 2), 256>>>(
        w_attn, waT, w_proj, wpT);

    // QKV: q columns pre-scaled by 0.125*log2e in epilogue
    gemm_f16d<true><<<dim3(C3_ / 128, MT_ / 128), 256, 98304>>>(
        xh, waT, b_attn, qkv_h, MT_, C3_, C_);

    // attention: paired q-tiles, shared KV loads
    attn_f16q2<<<dim3(TQ_ / 2, B_ * H_), 256>>>(qkv_h, att_h);

    // proj
    gemm_f16d<false><<<dim3(C_ / 128, MT_ / 128), 256, 98304>>>(
        att_h, wpT, b_proj, out, MT_, C_, C_);
}

// round 16
// speedup vs baseline: 1.0523x; 1.0523x over previous
#include <cuda_runtime.h>
#include <cuda_fp16.h>
#include <cstdint>

#define B_   8
#define T_   1024
#define C_   768
#define H_   12
#define D_   64
#define C3_  2304
#define MT_  (B_ * T_)      // 8192 rows
#define TQ_  (T_ / 64)      // 16 q-tiles
#define QSC_ 0.18033688011112042f   // 0.125 * log2(e)

__device__ __half g_qkv_h[(size_t)MT_ * C3_];  // [t][3C]; q pre-scaled by QSC_
__device__ __half g_att_h[(size_t)MT_ * C_];   // [t][C]
__device__ __half g_xh  [(size_t)MT_ * C_];    // x as fp16
__device__ __half g_waT [(size_t)C3_ * C_];    // w_attn^T  [N][K]
__device__ __half g_wpT [(size_t)C_  * C_];    // w_proj^T  [N][K]

// ---------------------------------------------------------------------------
__device__ __forceinline__ unsigned f2h2(float x, float y) {
    __half2 h = __floats2half2_rn(x, y);
    return *reinterpret_cast<unsigned*>(&h);
}
__device__ __forceinline__ uint32_t s2u(const void* p) {
    return (uint32_t)__cvta_generic_to_shared(p);
}
__device__ __forceinline__ void mma_f16(float c[4],
    unsigned a0, unsigned a1, unsigned a2, unsigned a3,
    unsigned b0, unsigned b1)
{
    asm volatile(
        "mma.sync.aligned.m16n8k16.row.col.f32.f16.f16.f32 "
        "{%0,%1,%2,%3}, {%4,%5,%6,%7}, {%8,%9}, {%0,%1,%2,%3};\n"
        : "+f"(c[0]), "+f"(c[1]), "+f"(c[2]), "+f"(c[3])
        : "r"(a0), "r"(a1), "r"(a2), "r"(a3), "r"(b0), "r"(b1));
}
__device__ __forceinline__ void ldsm_x4(unsigned& d0, unsigned& d1,
                                        unsigned& d2, unsigned& d3, unsigned saddr)
{
    asm volatile("ldmatrix.sync.aligned.m8n8.x4.shared.b16 {%0,%1,%2,%3}, [%4];\n"
                 : "=r"(d0), "=r"(d1), "=r"(d2), "=r"(d3) : "r"(saddr));
}
__device__ __forceinline__ void ldsm_x4_t(unsigned& d0, unsigned& d1,
                                          unsigned& d2, unsigned& d3, unsigned saddr)
{
    asm volatile("ldmatrix.sync.aligned.m8n8.x4.trans.shared.b16 {%0,%1,%2,%3}, [%4];\n"
                 : "=r"(d0), "=r"(d1), "=r"(d2), "=r"(d3) : "r"(saddr));
}
__device__ __forceinline__ void cp16(uint32_t saddr, const void* gaddr) {
    asm volatile("cp.async.cg.shared.global [%0], [%1], 16;"
                 :: "r"(saddr), "l"(gaddr));
}
#define CP_COMMIT()  asm volatile("cp.async.commit_group;" ::: "memory")
#define CP_WAIT0()   asm volatile("cp.async.wait_group 0;" ::: "memory")
#define CP_WAIT1()   asm volatile("cp.async.wait_group 1;" ::: "memory")

// ---------------------------------------------------------------------------
// prep kernels
// ---------------------------------------------------------------------------
__global__ void cvt_x_kernel(const float* __restrict__ x, __half* __restrict__ xh,
                             int n4) {
    int i = blockIdx.x * blockDim.x + threadIdx.x;
    if (i < n4) {
        float4 v = ((const float4*)x)[i];
        uint2 h;
        h.x = f2h2(v.x, v.y);
        h.y = f2h2(v.z, v.w);
        ((uint2*)xh)[i] = h;
    }
}

// z=0: w_attn (N=2304) -> waT ; z=1: w_proj (N=768) -> wpT
__global__ __launch_bounds__(256) void transpose_cvt2_kernel(
    const float* __restrict__ wa, __half* __restrict__ waT,
    const float* __restrict__ wp, __half* __restrict__ wpT)
{
    const float* w;  __half* wt;  int N;
    if (blockIdx.z == 0) { w = wa; wt = waT; N = C3_; }
    else                 { w = wp; wt = wpT; N = C_;  }
    int n0 = blockIdx.x * 32, k0 = blockIdx.y * 32;
    if (n0 >= N) return;
    __shared__ float tile[32][33];
    int tx = threadIdx.x & 31, ty = threadIdx.x >> 5;
    #pragma unroll
    for (int i = ty; i < 32; i += 8)
        tile[i][tx] = w[(size_t)(k0 + i) * N + n0 + tx];
    __syncthreads();
    #pragma unroll
    for (int i = ty; i < 32; i += 8)
        wt[(size_t)(n0 + i) * C_ + k0 + tx] = __float2half(tile[tx][i]);
}

// ---------------------------------------------------------------------------
// FP16 GEMM 128x128: BK=64, 3-stage cp.async ring, 96 KB dyn smem.
// HALF_OUT epilogue pre-scales q columns (col < 768) by QSC_ in fp32.
// ---------------------------------------------------------------------------
#define STAGEB 32768u

template<bool HALF_OUT>
__global__ __launch_bounds__(256, 2) void gemm_f16d(
    const __half* __restrict__ A, const __half* __restrict__ Bt,
    const float* __restrict__ bias, void* __restrict__ Cout,
    int M, int N, int K)
{
    extern __shared__ __align__(128) char dsm[];

    const int tid  = threadIdx.x;
    const int lane = tid & 31;
    const int wid  = tid >> 5;
    const int wm   = wid >> 2;
    const int wn   = wid & 3;
    const int g    = lane >> 2;
    const int t4   = lane & 3;
    const int l7   = lane & 7;
    const int lb8  = (lane >> 3) & 1;
    const int lb16 = (lane >> 4) & 1;

    const int rowBase = blockIdx.y * 128;
    const int colBase = blockIdx.x * 128;

    const unsigned Sb = s2u(dsm);

    float acc[4][4][4];
    #pragma unroll
    for (int i = 0; i < 4; i++)
        #pragma unroll
        for (int j = 0; j < 4; j++)
            #pragma unroll
            for (int q = 0; q < 4; q++) acc[i][j][q] = 0.f;

    const int ldR = tid >> 1;
    const int cb  = (tid & 1) * 4;
    unsigned soff[4];
    #pragma unroll
    for (int j = 0; j < 4; j++)
        soff[j] = (unsigned)(ldR * 128 + (((cb + j) ^ (ldR & 7)) << 4));
    const __half* gA = A  + (size_t)(rowBase + ldR) * K + (tid & 1) * 32;
    const __half* gB = Bt + (size_t)(colBase + ldR) * K + (tid & 1) * 32;

    #define ISSUE(s, wb) {                                        \
        const unsigned bo = (unsigned)(wb) * STAGEB;              \
        const __half* ga = gA + (size_t)(s) * 64;                 \
        const __half* gb = gB + (size_t)(s) * 64;                 \
        cp16(Sb + bo + soff[0], ga);                              \
        cp16(Sb + bo + soff[1], ga + 8);                          \
        cp16(Sb + bo + soff[2], ga + 16);                         \
        cp16(Sb + bo + soff[3], ga + 24);                         \
        cp16(Sb + bo + 16384u + soff[0], gb);                     \
        cp16(Sb + bo + 16384u + soff[1], gb + 8);                 \
        cp16(Sb + bo + 16384u + soff[2], gb + 16);                \
        cp16(Sb + bo + 16384u + soff[3], gb + 24);                \
        CP_COMMIT();                                              \
    }

    const int NS = K / 64;
    ISSUE(0, 0);
    ISSUE(1, 1);
    int wbuf = 2, rbuf = 0;

    const unsigned aRow = (unsigned)((wm * 64 + l7 + 8 * lb8) * 128);
    const unsigned bRow = (unsigned)((l7 + 8 * lb16) * 128) + 16384u;

    for (int s = 0; s < NS; s++) {
        if (s + 1 < NS) CP_WAIT1(); else CP_WAIT0();
        __syncthreads();
        if (s + 2 < NS) {
            ISSUE(s + 2, wbuf);
            wbuf = (wbuf == 2) ? 0 : wbuf + 1;
        }

        const unsigned base = Sb + (unsigned)rbuf * STAGEB;
        const unsigned aw = base + aRow;
        const unsigned bw = base + bRow;
        #pragma unroll
        for (int kb = 0; kb < 4; kb++) {
            const unsigned ach = (unsigned)(((kb * 2 + lb16) ^ l7) << 4);
            const unsigned bch = (unsigned)(((kb * 2 + lb8)  ^ l7) << 4);
            unsigned af[4][4];
            #pragma unroll
            for (int mt = 0; mt < 4; mt++)
                ldsm_x4(af[mt][0], af[mt][1], af[mt][2], af[mt][3],
                        aw + (unsigned)(mt * 2048) + ach);
            unsigned bf[4][2];
            #pragma unroll
            for (int ntp = 0; ntp < 2; ntp++) {
                unsigned d0, d1, d2, d3;
                ldsm_x4(d0, d1, d2, d3,
                        bw + (unsigned)((wn * 32 + ntp * 16) * 128) + bch);
                bf[ntp * 2 + 0][0] = d0; bf[ntp * 2 + 0][1] = d1;
                bf[ntp * 2 + 1][0] = d2; bf[ntp * 2 + 1][1] = d3;
            }
            #pragma unroll
            for (int mt = 0; mt < 4; mt++)
                #pragma unroll
                for (int nt = 0; nt < 4; nt++)
                    mma_f16(acc[mt][nt], af[mt][0], af[mt][1], af[mt][2], af[mt][3],
                            bf[nt][0], bf[nt][1]);
        }
        rbuf = (rbuf == 2) ? 0 : rbuf + 1;
    }
    #undef ISSUE

    #pragma unroll
    for (int mt = 0; mt < 4; mt++) {
        #pragma unroll
        for (int nt = 0; nt < 4; nt++) {
            int r0 = rowBase + wm * 64 + mt * 16 + g;
            int c  = colBase + wn * 32 + nt * 8 + 2 * t4;
            float bx = bias[c], by = bias[c + 1];
            if (HALF_OUT) {
                float sc = (c < C_) ? QSC_ : 1.0f;   // pre-scale q columns
                __half* out = (__half*)Cout;
                *(unsigned*)(out + (size_t)r0 * N + c) =
                    f2h2((acc[mt][nt][0] + bx) * sc, (acc[mt][nt][1] + by) * sc);
                *(unsigned*)(out + (size_t)(r0 + 8) * N + c) =
                    f2h2((acc[mt][nt][2] + bx) * sc, (acc[mt][nt][3] + by) * sc);
            } else {
                float* out = (float*)Cout;
                *(float2*)(out + (size_t)r0 * N + c) =
                    make_float2(acc[mt][nt][0] + bx, acc[mt][nt][1] + by);
                *(float2*)(out + (size_t)(r0 + 8) * N + c) =
                    make_float2(acc[mt][nt][2] + bx, acc[mt][nt][3] + by);
            }
        }
    }
}

// ---------------------------------------------------------------------------
// Flash causal attention (R14 structure), exp2-domain softmax, P kept in
// registers via the C-frag == A-frag identity (no smem round-trip).
// 128 threads = 4 warps, 64 q-rows/block, 32-key tiles, double-buffered K/V.
// ---------------------------------------------------------------------------
#define QST2 72
#define KST2 72

__global__ __launch_bounds__(128) void attn_f16(
    const __half* __restrict__ qkv, __half* __restrict__ outp)
{
    __shared__ __align__(16) __half Qs[64 * QST2];
    __shared__ __align__(16) __half Ks[2][32 * KST2];
    __shared__ __align__(16) __half Vs[2][32 * KST2];
    const unsigned KVB = 32 * KST2 * 2;

    const int tid  = threadIdx.x;
    const int lane = tid & 31;
    const int wid  = tid >> 5;
    const int g    = lane >> 2;
    const int t4   = lane & 3;

    const int bh = blockIdx.y;
    const int b  = bh / H_;
    const int h  = bh % H_;
    const int qt = blockIdx.x;
    const int qBase = qt * 64;

    const __half* qptr = qkv + (size_t)b * T_ * C3_ + h * D_;
    const __half* kptr = qptr + C_;
    const __half* vptr = qptr + 2 * C_;

    const unsigned qoff = ((lane & 7) + ((lane >> 3) & 1) * 8) * QST2
                        + ((lane >> 4) & 1) * 8;
    const unsigned koff = ((lane & 7) + ((lane >> 4) & 1) * 8) * KST2
                        + ((lane >> 3) & 1) * 8;
    const unsigned voff = ((lane & 7) + ((lane >> 3) & 1) * 8) * KST2
                        + ((lane >> 4) & 1) * 8;
    const unsigned Qs_base = s2u(&Qs[0]);
    const unsigned Ks_base = s2u(&Ks[0][0]);
    const unsigned Vs_base = s2u(&Vs[0][0]);

    const int r0l = tid >> 3;
    const int c8l = (tid & 7) << 3;
    const unsigned sK0 = Ks_base + (unsigned)(r0l * KST2 + c8l) * 2;
    const unsigned sK1 = Ks_base + (unsigned)((r0l + 16) * KST2 + c8l) * 2;
    const unsigned sV0 = Vs_base + (unsigned)(r0l * KST2 + c8l) * 2;
    const unsigned sV1 = Vs_base + (unsigned)((r0l + 16) * KST2 + c8l) * 2;

    #define AISSUE(kt, wb) {                                                  \
        const unsigned bo = (unsigned)(wb) * KVB;                             \
        const __half* gk0 = kptr + (size_t)((kt) * 32 + r0l) * C3_ + c8l;     \
        const __half* gv0 = vptr + (size_t)((kt) * 32 + r0l) * C3_ + c8l;     \
        cp16(sK0 + bo, gk0);                                                  \
        cp16(sK1 + bo, gk0 + 16 * C3_);                                       \
        cp16(sV0 + bo, gv0);                                                  \
        cp16(sV1 + bo, gv0 + 16 * C3_);                                       \
        CP_COMMIT();                                                          \
    }

    #pragma unroll
    for (int l = 0; l < 4; l++) {
        int idx = tid + l * 128;
        int r = idx >> 3, c8 = (idx & 7) << 3;
        *(uint4*)&Qs[r * QST2 + c8] =
            *(const uint4*)(qptr + (size_t)(qBase + r) * C3_ + c8);
    }
    AISSUE(0, 0);
    __syncthreads();

    unsigned qa[4][4];
    #pragma unroll
    for (int kq = 0; kq < 4; kq++)
        ldsm_x4(qa[kq][0], qa[kq][1], qa[kq][2], qa[kq][3],
                Qs_base + (qoff + (unsigned)(wid * 16 * QST2 + kq * 16)) * 2);

    float o[8][4];
    #pragma unroll
    for (int nt = 0; nt < 8; nt++)
        #pragma unroll
        for (int q = 0; q < 4; q++) o[nt][q] = 0.f;
    float m0 = -1e30f, m1 = -1e30f, l0 = 0.f, l1 = 0.f;

    const int rowL = wid * 16 + g;
    const int row0 = qBase + rowL;
    const int row1 = row0 + 8;

    const int ktmax = 2 * qt + 1;
    for (int kt = 0; kt <= ktmax; kt++) {
        const int kBase = kt * 32;
        const bool domask = (kt >= 2 * qt);
        const unsigned rb = (unsigned)(kt & 1) * KVB;

        CP_WAIT0();
        __syncthreads();
        if (kt + 1 <= ktmax) AISSUE(kt + 1, (kt + 1) & 1);

        // S = q_scaled @ K^T  (already in log2 domain)
        float s[4][4];
        #pragma unroll
        for (int nt = 0; nt < 4; nt++)
            #pragma unroll
            for (int q = 0; q < 4; q++) s[nt][q] = 0.f;

        #pragma unroll
        for (int kq = 0; kq < 4; kq++) {
            #pragma unroll
            for (int ntp = 0; ntp < 2; ntp++) {
                unsigned d0, d1, d2, d3;
                ldsm_x4(d0, d1, d2, d3,
                        Ks_base + rb + (koff + (unsigned)(ntp * 16 * KST2 + kq * 16)) * 2);
                mma_f16(s[ntp * 2 + 0], qa[kq][0], qa[kq][1], qa[kq][2], qa[kq][3],
                        d0, d1);
                mma_f16(s[ntp * 2 + 1], qa[kq][0], qa[kq][1], qa[kq][2], qa[kq][3],
                        d2, d3);
            }
        }

        // causal mask only (scale folded into q)
        if (domask) {
            #pragma unroll
            for (int nt = 0; nt < 4; nt++) {
                #pragma unroll
                for (int q = 0; q < 4; q++) {
                    int col = kBase + nt * 8 + 2 * t4 + (q & 1);
                    int row = (q < 2) ? row0 : row1;
                    if (col > row) s[nt][q] = -1e30f;
                }
            }
        }

        // online softmax in exp2 domain
        float mt0 = -1e30f, mt1 = -1e30f;
        #pragma unroll
        for (int nt = 0; nt < 4; nt++) {
            mt0 = fmaxf(mt0, fmaxf(s[nt][0], s[nt][1]));
            mt1 = fmaxf(mt1, fmaxf(s[nt][2], s[nt][3]));
        }
        mt0 = fmaxf(mt0, __shfl_xor_sync(0xffffffffu, mt0, 1));
        mt0 = fmaxf(mt0, __shfl_xor_sync(0xffffffffu, mt0, 2));
        mt1 = fmaxf(mt1, __shfl_xor_sync(0xffffffffu, mt1, 1));
        mt1 = fmaxf(mt1, __shfl_xor_sync(0xffffffffu, mt1, 2));

        float mn0 = fmaxf(m0, mt0), mn1 = fmaxf(m1, mt1);
        float al0 = exp2f(m0 - mn0), al1 = exp2f(m1 - mn1);
        m0 = mn0; m1 = mn1;

        float rs0 = 0.f, rs1 = 0.f;
        #pragma unroll
        for (int nt = 0; nt < 4; nt++) {
            s[nt][0] = exp2f(s[nt][0] - mn0);
            s[nt][1] = exp2f(s[nt][1] - mn0);
            s[nt][2] = exp2f(s[nt][2] - mn1);
            s[nt][3] = exp2f(s[nt][3] - mn1);
            rs0 += s[nt][0] + s[nt][1];
            rs1 += s[nt][2] + s[nt][3];
        }
        rs0 += __shfl_xor_sync(0xffffffffu, rs0, 1);
        rs0 += __shfl_xor_sync(0xffffffffu, rs0, 2);
        rs1 += __shfl_xor_sync(0xffffffffu, rs1, 1);
        rs1 += __shfl_xor_sync(0xffffffffu, rs1, 2);
        l0 = l0 * al0 + rs0;
        l1 = l1 * al1 + rs1;

        #pragma unroll
        for (int nt = 0; nt < 8; nt++) {
            o[nt][0] *= al0; o[nt][1] *= al0;
            o[nt][2] *= al1; o[nt][3] *= al1;
        }

        // O += P @ V : P packed straight from S C-fragments (register identity)
        #pragma unroll
        for (int kb = 0; kb < 2; kb++) {
            unsigned a0 = f2h2(s[2 * kb    ][0], s[2 * kb    ][1]);
            unsigned a1 = f2h2(s[2 * kb    ][2], s[2 * kb    ][3]);
            unsigned a2 = f2h2(s[2 * kb + 1][0], s[2 * kb + 1][1]);
            unsigned a3 = f2h2(s[2 * kb + 1][2], s[2 * kb + 1][3]);
            #pragma unroll
            for (int ntp = 0; ntp < 4; ntp++) {
                unsigned d0, d1, d2, d3;
                ldsm_x4_t(d0, d1, d2, d3,
                          Vs_base + rb + (voff + (unsigned)(kb * 16 * KST2 + ntp * 16)) * 2);
                mma_f16(o[ntp * 2 + 0], a0, a1, a2, a3, d0, d1);
                mma_f16(o[ntp * 2 + 1], a0, a1, a2, a3, d2, d3);
            }
        }
    }
    #undef AISSUE

    float inv0 = 1.f / l0, inv1 = 1.f / l1;
    #pragma unroll
    for (int nt = 0; nt < 8; nt++) {
        int d = nt * 8 + 2 * t4;
        unsigned u0 = f2h2(o[nt][0] * inv0, o[nt][1] * inv0);
        unsigned u1 = f2h2(o[nt][2] * inv1, o[nt][3] * inv1);
        *(unsigned*)(outp + ((size_t)b * T_ + row0) * C_ + h * D_ + d) = u0;
        *(unsigned*)(outp + ((size_t)b * T_ + row1) * C_ + h * D_ + d) = u1;
    }
}

// ---------------------------------------------------------------------------
extern "C" void kernel_launch(void* const* d_in, const int* in_sizes, int n_in,
                              void* d_out, int out_size)
{
    (void)in_sizes; (void)n_in; (void)out_size;
    const float* x      = (const float*)d_in[0];
    const float* w_attn = (const float*)d_in[1];
    const float* b_attn = (const float*)d_in[2];
    const float* w_proj = (const float*)d_in[3];
    const float* b_proj = (const float*)d_in[4];
    float* out = (float*)d_out;

    __half *qkv_h, *att_h, *xh, *waT, *wpT;
    cudaGetSymbolAddress((void**)&qkv_h, g_qkv_h);
    cudaGetSymbolAddress((void**)&att_h, g_att_h);
    cudaGetSymbolAddress((void**)&xh,    g_xh);
    cudaGetSymbolAddress((void**)&waT,   g_waT);
    cudaGetSymbolAddress((void**)&wpT,   g_wpT);

    cudaFuncSetAttribute(gemm_f16d<true>,
                         cudaFuncAttributeMaxDynamicSharedMemorySize, 98304);
    cudaFuncSetAttribute(gemm_f16d<false>,
                         cudaFuncAttributeMaxDynamicSharedMemorySize, 98304);

    const int n4 = MT_ * C_ / 4;
    cvt_x_kernel<<<(n4 + 255) / 256, 256>>>(x, xh, n4);
    transpose_cvt2_kernel<<<dim3(C3_ / 32, C_ / 32, 2), 256>>>(
        w_attn, waT, w_proj, wpT);

    // QKV: q columns pre-scaled by 0.125*log2e in epilogue
    gemm_f16d<true><<<dim3(C3_ / 128, MT_ / 128), 256, 98304>>>(
        xh, waT, b_attn, qkv_h, MT_, C3_, C_);

    attn_f16<<<dim3(TQ_, B_ * H_), 128>>>(qkv_h, att_h);

    // proj
    gemm_f16d<false><<<dim3(C_ / 128, MT_ / 128), 256, 98304>>>(
        att_h, wpT, b_proj, out, MT_, C_, C_);
}

// round 17
// speedup vs baseline: 1.0536x; 1.0013x over previous
#include <cuda_runtime.h>
#include <cuda_fp16.h>
#include <cstdint>

#define B_   8
#define T_   1024
#define C_   768
#define H_   12
#define D_   64
#define C3_  2304
#define MT_  (B_ * T_)      // 8192 rows
#define TQ_  (T_ / 64)      // 16 q-tiles
#define QSC_ 0.18033688011112042f   // 0.125 * log2(e)

__device__ __half g_qkv_h[(size_t)MT_ * C3_];  // [t][3C]; q pre-scaled by QSC_
__device__ __half g_att_h[(size_t)MT_ * C_];   // [t][C]
__device__ __half g_xh  [(size_t)MT_ * C_];    // x as fp16
__device__ __half g_waT [(size_t)C3_ * C_];    // w_attn^T  [N][K]
__device__ __half g_wpT [(size_t)C_  * C_];    // w_proj^T  [N][K]

// ---------------------------------------------------------------------------
__device__ __forceinline__ unsigned f2h2(float x, float y) {
    __half2 h = __floats2half2_rn(x, y);
    return *reinterpret_cast<unsigned*>(&h);
}
__device__ __forceinline__ float ex2(float x) {
    float y;
    asm("ex2.approx.f32 %0, %1;" : "=f"(y) : "f"(x));
    return y;
}
__device__ __forceinline__ uint32_t s2u(const void* p) {
    return (uint32_t)__cvta_generic_to_shared(p);
}
__device__ __forceinline__ void mma_f16(float c[4],
    unsigned a0, unsigned a1, unsigned a2, unsigned a3,
    unsigned b0, unsigned b1)
{
    asm volatile(
        "mma.sync.aligned.m16n8k16.row.col.f32.f16.f16.f32 "
        "{%0,%1,%2,%3}, {%4,%5,%6,%7}, {%8,%9}, {%0,%1,%2,%3};\n"
        : "+f"(c[0]), "+f"(c[1]), "+f"(c[2]), "+f"(c[3])
        : "r"(a0), "r"(a1), "r"(a2), "r"(a3), "r"(b0), "r"(b1));
}
__device__ __forceinline__ void ldsm_x4(unsigned& d0, unsigned& d1,
                                        unsigned& d2, unsigned& d3, unsigned saddr)
{
    asm volatile("ldmatrix.sync.aligned.m8n8.x4.shared.b16 {%0,%1,%2,%3}, [%4];\n"
                 : "=r"(d0), "=r"(d1), "=r"(d2), "=r"(d3) : "r"(saddr));
}
__device__ __forceinline__ void ldsm_x4_t(unsigned& d0, unsigned& d1,
                                          unsigned& d2, unsigned& d3, unsigned saddr)
{
    asm volatile("ldmatrix.sync.aligned.m8n8.x4.trans.shared.b16 {%0,%1,%2,%3}, [%4];\n"
                 : "=r"(d0), "=r"(d1), "=r"(d2), "=r"(d3) : "r"(saddr));
}
__device__ __forceinline__ void cp16(uint32_t saddr, const void* gaddr) {
    asm volatile("cp.async.cg.shared.global [%0], [%1], 16;"
                 :: "r"(saddr), "l"(gaddr));
}
#define CP_COMMIT()  asm volatile("cp.async.commit_group;" ::: "memory")
#define CP_WAIT0()   asm volatile("cp.async.wait_group 0;" ::: "memory")
#define CP_WAIT1()   asm volatile("cp.async.wait_group 1;" ::: "memory")

// ---------------------------------------------------------------------------
// prep kernels
// ---------------------------------------------------------------------------
__global__ void cvt_x_kernel(const float* __restrict__ x, __half* __restrict__ xh,
                             int n4) {
    int i = blockIdx.x * blockDim.x + threadIdx.x;
    if (i < n4) {
        float4 v = ((const float4*)x)[i];
        uint2 h;
        h.x = f2h2(v.x, v.y);
        h.y = f2h2(v.z, v.w);
        ((uint2*)xh)[i] = h;
    }
}

// z=0: w_attn (N=2304) -> waT ; z=1: w_proj (N=768) -> wpT
__global__ __launch_bounds__(256) void transpose_cvt2_kernel(
    const float* __restrict__ wa, __half* __restrict__ waT,
    const float* __restrict__ wp, __half* __restrict__ wpT)
{
    const float* w;  __half* wt;  int N;
    if (blockIdx.z == 0) { w = wa; wt = waT; N = C3_; }
    else                 { w = wp; wt = wpT; N = C_;  }
    int n0 = blockIdx.x * 32, k0 = blockIdx.y * 32;
    if (n0 >= N) return;
    __shared__ float tile[32][33];
    int tx = threadIdx.x & 31, ty = threadIdx.x >> 5;
    #pragma unroll
    for (int i = ty; i < 32; i += 8)
        tile[i][tx] = w[(size_t)(k0 + i) * N + n0 + tx];
    __syncthreads();
    #pragma unroll
    for (int i = ty; i < 32; i += 8)
        wt[(size_t)(n0 + i) * C_ + k0 + tx] = __float2half(tile[tx][i]);
}

// ---------------------------------------------------------------------------
// FP16 GEMM 128x128: BK=64, 3-stage cp.async ring, 96 KB dyn smem.
// HALF_OUT epilogue pre-scales q columns (col < 768) by QSC_ in fp32.
// ---------------------------------------------------------------------------
#define STAGEB 32768u

template<bool HALF_OUT>
__global__ __launch_bounds__(256, 2) void gemm_f16d(
    const __half* __restrict__ A, const __half* __restrict__ Bt,
    const float* __restrict__ bias, void* __restrict__ Cout,
    int M, int N, int K)
{
    extern __shared__ __align__(128) char dsm[];

    const int tid  = threadIdx.x;
    const int lane = tid & 31;
    const int wid  = tid >> 5;
    const int wm   = wid >> 2;
    const int wn   = wid & 3;
    const int g    = lane >> 2;
    const int t4   = lane & 3;
    const int l7   = lane & 7;
    const int lb8  = (lane >> 3) & 1;
    const int lb16 = (lane >> 4) & 1;

    const int rowBase = blockIdx.y * 128;
    const int colBase = blockIdx.x * 128;

    const unsigned Sb = s2u(dsm);

    float acc[4][4][4];
    #pragma unroll
    for (int i = 0; i < 4; i++)
        #pragma unroll
        for (int j = 0; j < 4; j++)
            #pragma unroll
            for (int q = 0; q < 4; q++) acc[i][j][q] = 0.f;

    const int ldR = tid >> 1;
    const int cb  = (tid & 1) * 4;
    unsigned soff[4];
    #pragma unroll
    for (int j = 0; j < 4; j++)
        soff[j] = (unsigned)(ldR * 128 + (((cb + j) ^ (ldR & 7)) << 4));
    const __half* gA = A  + (size_t)(rowBase + ldR) * K + (tid & 1) * 32;
    const __half* gB = Bt + (size_t)(colBase + ldR) * K + (tid & 1) * 32;

    #define ISSUE(s, wb) {                                        \
        const unsigned bo = (unsigned)(wb) * STAGEB;              \
        const __half* ga = gA + (size_t)(s) * 64;                 \
        const __half* gb = gB + (size_t)(s) * 64;                 \
        cp16(Sb + bo + soff[0], ga);                              \
        cp16(Sb + bo + soff[1], ga + 8);                          \
        cp16(Sb + bo + soff[2], ga + 16);                         \
        cp16(Sb + bo + soff[3], ga + 24);                         \
        cp16(Sb + bo + 16384u + soff[0], gb);                     \
        cp16(Sb + bo + 16384u + soff[1], gb + 8);                 \
        cp16(Sb + bo + 16384u + soff[2], gb + 16);                \
        cp16(Sb + bo + 16384u + soff[3], gb + 24);                \
        CP_COMMIT();                                              \
    }

    const int NS = K / 64;
    ISSUE(0, 0);
    ISSUE(1, 1);
    int wbuf = 2, rbuf = 0;

    const unsigned aRow = (unsigned)((wm * 64 + l7 + 8 * lb8) * 128);
    const unsigned bRow = (unsigned)((l7 + 8 * lb16) * 128) + 16384u;

    for (int s = 0; s < NS; s++) {
        if (s + 1 < NS) CP_WAIT1(); else CP_WAIT0();
        __syncthreads();
        if (s + 2 < NS) {
            ISSUE(s + 2, wbuf);
            wbuf = (wbuf == 2) ? 0 : wbuf + 1;
        }

        const unsigned base = Sb + (unsigned)rbuf * STAGEB;
        const unsigned aw = base + aRow;
        const unsigned bw = base + bRow;
        #pragma unroll
        for (int kb = 0; kb < 4; kb++) {
            const unsigned ach = (unsigned)(((kb * 2 + lb16) ^ l7) << 4);
            const unsigned bch = (unsigned)(((kb * 2 + lb8)  ^ l7) << 4);
            unsigned af[4][4];
            #pragma unroll
            for (int mt = 0; mt < 4; mt++)
                ldsm_x4(af[mt][0], af[mt][1], af[mt][2], af[mt][3],
                        aw + (unsigned)(mt * 2048) + ach);
            unsigned bf[4][2];
            #pragma unroll
            for (int ntp = 0; ntp < 2; ntp++) {
                unsigned d0, d1, d2, d3;
                ldsm_x4(d0, d1, d2, d3,
                        bw + (unsigned)((wn * 32 + ntp * 16) * 128) + bch);
                bf[ntp * 2 + 0][0] = d0; bf[ntp * 2 + 0][1] = d1;
                bf[ntp * 2 + 1][0] = d2; bf[ntp * 2 + 1][1] = d3;
            }
            #pragma unroll
            for (int mt = 0; mt < 4; mt++)
                #pragma unroll
                for (int nt = 0; nt < 4; nt++)
                    mma_f16(acc[mt][nt], af[mt][0], af[mt][1], af[mt][2], af[mt][3],
                            bf[nt][0], bf[nt][1]);
        }
        rbuf = (rbuf == 2) ? 0 : rbuf + 1;
    }
    #undef ISSUE

    #pragma unroll
    for (int mt = 0; mt < 4; mt++) {
        #pragma unroll
        for (int nt = 0; nt < 4; nt++) {
            int r0 = rowBase + wm * 64 + mt * 16 + g;
            int c  = colBase + wn * 32 + nt * 8 + 2 * t4;
            float bx = bias[c], by = bias[c + 1];
            if (HALF_OUT) {
                float sc = (c < C_) ? QSC_ : 1.0f;   // pre-scale q columns
                __half* out = (__half*)Cout;
                *(unsigned*)(out + (size_t)r0 * N + c) =
                    f2h2((acc[mt][nt][0] + bx) * sc, (acc[mt][nt][1] + by) * sc);
                *(unsigned*)(out + (size_t)(r0 + 8) * N + c) =
                    f2h2((acc[mt][nt][2] + bx) * sc, (acc[mt][nt][3] + by) * sc);
            } else {
                float* out = (float*)Cout;
                *(float2*)(out + (size_t)r0 * N + c) =
                    make_float2(acc[mt][nt][0] + bx, acc[mt][nt][1] + by);
                *(float2*)(out + (size_t)(r0 + 8) * N + c) =
                    make_float2(acc[mt][nt][2] + bx, acc[mt][nt][3] + by);
            }
        }
    }
}

// ---------------------------------------------------------------------------
// Flash causal attention: exp2-domain softmax (ex2.approx), register-resident
// P (C-frag == A-frag identity), V fragments hoisted before softmax so their
// smem latency overlaps the softmax dependency chain.
// 128 threads = 4 warps, 64 q-rows/block, 32-key tiles, double-buffered K/V.
// ---------------------------------------------------------------------------
#define QST2 72
#define KST2 72

__global__ __launch_bounds__(128) void attn_f16(
    const __half* __restrict__ qkv, __half* __restrict__ outp)
{
    __shared__ __align__(16) __half Qs[64 * QST2];
    __shared__ __align__(16) __half Ks[2][32 * KST2];
    __shared__ __align__(16) __half Vs[2][32 * KST2];
    const unsigned KVB = 32 * KST2 * 2;

    const int tid  = threadIdx.x;
    const int lane = tid & 31;
    const int wid  = tid >> 5;
    const int g    = lane >> 2;
    const int t4   = lane & 3;

    const int bh = blockIdx.y;
    const int b  = bh / H_;
    const int h  = bh % H_;
    const int qt = blockIdx.x;
    const int qBase = qt * 64;

    const __half* qptr = qkv + (size_t)b * T_ * C3_ + h * D_;
    const __half* kptr = qptr + C_;
    const __half* vptr = qptr + 2 * C_;

    const unsigned qoff = ((lane & 7) + ((lane >> 3) & 1) * 8) * QST2
                        + ((lane >> 4) & 1) * 8;
    const unsigned koff = ((lane & 7) + ((lane >> 4) & 1) * 8) * KST2
                        + ((lane >> 3) & 1) * 8;
    const unsigned voff = ((lane & 7) + ((lane >> 3) & 1) * 8) * KST2
                        + ((lane >> 4) & 1) * 8;
    const unsigned Qs_base = s2u(&Qs[0]);
    const unsigned Ks_base = s2u(&Ks[0][0]);
    const unsigned Vs_base = s2u(&Vs[0][0]);

    const int r0l = tid >> 3;
    const int c8l = (tid & 7) << 3;
    const unsigned sK0 = Ks_base + (unsigned)(r0l * KST2 + c8l) * 2;
    const unsigned sK1 = Ks_base + (unsigned)((r0l + 16) * KST2 + c8l) * 2;
    const unsigned sV0 = Vs_base + (unsigned)(r0l * KST2 + c8l) * 2;
    const unsigned sV1 = Vs_base + (unsigned)((r0l + 16) * KST2 + c8l) * 2;

    #define AISSUE(kt, wb) {                                                  \
        const unsigned bo = (unsigned)(wb) * KVB;                             \
        const __half* gk0 = kptr + (size_t)((kt) * 32 + r0l) * C3_ + c8l;     \
        const __half* gv0 = vptr + (size_t)((kt) * 32 + r0l) * C3_ + c8l;     \
        cp16(sK0 + bo, gk0);                                                  \
        cp16(sK1 + bo, gk0 + 16 * C3_);                                       \
        cp16(sV0 + bo, gv0);                                                  \
        cp16(sV1 + bo, gv0 + 16 * C3_);                                       \
        CP_COMMIT();                                                          \
    }

    #pragma unroll
    for (int l = 0; l < 4; l++) {
        int idx = tid + l * 128;
        int r = idx >> 3, c8 = (idx & 7) << 3;
        *(uint4*)&Qs[r * QST2 + c8] =
            *(const uint4*)(qptr + (size_t)(qBase + r) * C3_ + c8);
    }
    AISSUE(0, 0);
    __syncthreads();

    unsigned qa[4][4];
    #pragma unroll
    for (int kq = 0; kq < 4; kq++)
        ldsm_x4(qa[kq][0], qa[kq][1], qa[kq][2], qa[kq][3],
                Qs_base + (qoff + (unsigned)(wid * 16 * QST2 + kq * 16)) * 2);

    float o[8][4];
    #pragma unroll
    for (int nt = 0; nt < 8; nt++)
        #pragma unroll
        for (int q = 0; q < 4; q++) o[nt][q] = 0.f;
    float m0 = -1e30f, m1 = -1e30f, l0 = 0.f, l1 = 0.f;

    const int rowL = wid * 16 + g;
    const int row0 = qBase + rowL;
    const int row1 = row0 + 8;

    const int ktmax = 2 * qt + 1;
    for (int kt = 0; kt <= ktmax; kt++) {
        const int kBase = kt * 32;
        const bool domask = (kt >= 2 * qt);
        const unsigned rb = (unsigned)(kt & 1) * KVB;

        CP_WAIT0();
        __syncthreads();
        if (kt + 1 <= ktmax) AISSUE(kt + 1, (kt + 1) & 1);

        // S = q_scaled @ K^T  (already in log2 domain)
        float s[4][4];
        #pragma unroll
        for (int nt = 0; nt < 4; nt++)
            #pragma unroll
            for (int q = 0; q < 4; q++) s[nt][q] = 0.f;

        #pragma unroll
        for (int kq = 0; kq < 4; kq++) {
            #pragma unroll
            for (int ntp = 0; ntp < 2; ntp++) {
                unsigned d0, d1, d2, d3;
                ldsm_x4(d0, d1, d2, d3,
                        Ks_base + rb + (koff + (unsigned)(ntp * 16 * KST2 + kq * 16)) * 2);
                mma_f16(s[ntp * 2 + 0], qa[kq][0], qa[kq][1], qa[kq][2], qa[kq][3],
                        d0, d1);
                mma_f16(s[ntp * 2 + 1], qa[kq][0], qa[kq][1], qa[kq][2], qa[kq][3],
                        d2, d3);
            }
        }

        // hoist V fragments now — no dependence on softmax; latency overlaps it
        unsigned vf[2][4][4];
        #pragma unroll
        for (int kb = 0; kb < 2; kb++)
            #pragma unroll
            for (int ntp = 0; ntp < 4; ntp++)
                ldsm_x4_t(vf[kb][ntp][0], vf[kb][ntp][1],
                          vf[kb][ntp][2], vf[kb][ntp][3],
                          Vs_base + rb + (voff + (unsigned)(kb * 16 * KST2 + ntp * 16)) * 2);

        // causal mask only (scale folded into q)
        if (domask) {
            #pragma unroll
            for (int nt = 0; nt < 4; nt++) {
                #pragma unroll
                for (int q = 0; q < 4; q++) {
                    int col = kBase + nt * 8 + 2 * t4 + (q & 1);
                    int row = (q < 2) ? row0 : row1;
                    if (col > row) s[nt][q] = -1e30f;
                }
            }
        }

        // online softmax in exp2 domain (ex2.approx)
        float mt0 = -1e30f, mt1 = -1e30f;
        #pragma unroll
        for (int nt = 0; nt < 4; nt++) {
            mt0 = fmaxf(mt0, fmaxf(s[nt][0], s[nt][1]));
            mt1 = fmaxf(mt1, fmaxf(s[nt][2], s[nt][3]));
        }
        mt0 = fmaxf(mt0, __shfl_xor_sync(0xffffffffu, mt0, 1));
        mt0 = fmaxf(mt0, __shfl_xor_sync(0xffffffffu, mt0, 2));
        mt1 = fmaxf(mt1, __shfl_xor_sync(0xffffffffu, mt1, 1));
        mt1 = fmaxf(mt1, __shfl_xor_sync(0xffffffffu, mt1, 2));

        float mn0 = fmaxf(m0, mt0), mn1 = fmaxf(m1, mt1);
        float al0 = ex2(m0 - mn0), al1 = ex2(m1 - mn1);
        m0 = mn0; m1 = mn1;

        float rs0 = 0.f, rs1 = 0.f;
        #pragma unroll
        for (int nt = 0; nt < 4; nt++) {
            s[nt][0] = ex2(s[nt][0] - mn0);
            s[nt][1] = ex2(s[nt][1] - mn0);
            s[nt][2] = ex2(s[nt][2] - mn1);
            s[nt][3] = ex2(s[nt][3] - mn1);
            rs0 += s[nt][0] + s[nt][1];
            rs1 += s[nt][2] + s[nt][3];
        }
        rs0 += __shfl_xor_sync(0xffffffffu, rs0, 1);
        rs0 += __shfl_xor_sync(0xffffffffu, rs0, 2);
        rs1 += __shfl_xor_sync(0xffffffffu, rs1, 1);
        rs1 += __shfl_xor_sync(0xffffffffu, rs1, 2);
        l0 = l0 * al0 + rs0;
        l1 = l1 * al1 + rs1;

        #pragma unroll
        for (int nt = 0; nt < 8; nt++) {
            o[nt][0] *= al0; o[nt][1] *= al0;
            o[nt][2] *= al1; o[nt][3] *= al1;
        }

        // O += P @ V : P packed straight from S C-fragments (register identity)
        #pragma unroll
        for (int kb = 0; kb < 2; kb++) {
            unsigned a0 = f2h2(s[2 * kb    ][0], s[2 * kb    ][1]);
            unsigned a1 = f2h2(s[2 * kb    ][2], s[2 * kb    ][3]);
            unsigned a2 = f2h2(s[2 * kb + 1][0], s[2 * kb + 1][1]);
            unsigned a3 = f2h2(s[2 * kb + 1][2], s[2 * kb + 1][3]);
            #pragma unroll
            for (int ntp = 0; ntp < 4; ntp++) {
                mma_f16(o[ntp * 2 + 0], a0, a1, a2, a3,
                        vf[kb][ntp][0], vf[kb][ntp][1]);
                mma_f16(o[ntp * 2 + 1], a0, a1, a2, a3,
                        vf[kb][ntp][2], vf[kb][ntp][3]);
            }
        }
    }
    #undef AISSUE

    float inv0 = 1.f / l0, inv1 = 1.f / l1;
    #pragma unroll
    for (int nt = 0; nt < 8; nt++) {
        int d = nt * 8 + 2 * t4;
        unsigned u0 = f2h2(o[nt][0] * inv0, o[nt][1] * inv0);
        unsigned u1 = f2h2(o[nt][2] * inv1, o[nt][3] * inv1);
        *(unsigned*)(outp + ((size_t)b * T_ + row0) * C_ + h * D_ + d) = u0;
        *(unsigned*)(outp + ((size_t)b * T_ + row1) * C_ + h * D_ + d) = u1;
    }
}

// ---------------------------------------------------------------------------
extern "C" void kernel_launch(void* const* d_in, const int* in_sizes, int n_in,
                              void* d_out, int out_size)
{
    (void)in_sizes; (void)n_in; (void)out_size;
    const float* x      = (const float*)d_in[0];
    const float* w_attn = (const float*)d_in[1];
    const float* b_attn = (const float*)d_in[2];
    const float* w_proj = (const float*)d_in[3];
    const float* b_proj = (const float*)d_in[4];
    float* out = (float*)d_out;

    __half *qkv_h, *att_h, *xh, *waT, *wpT;
    cudaGetSymbolAddress((void**)&qkv_h, g_qkv_h);
    cudaGetSymbolAddress((void**)&att_h, g_att_h);
    cudaGetSymbolAddress((void**)&xh,    g_xh);
    cudaGetSymbolAddress((void**)&waT,   g_waT);
    cudaGetSymbolAddress((void**)&wpT,   g_wpT);

    cudaFuncSetAttribute(gemm_f16d<true>,
                         cudaFuncAttributeMaxDynamicSharedMemorySize, 98304);
    cudaFuncSetAttribute(gemm_f16d<false>,
                         cudaFuncAttributeMaxDynamicSharedMemorySize, 98304);

    const int n4 = MT_ * C_ / 4;
    cvt_x_kernel<<<(n4 + 255) / 256, 256>>>(x, xh, n4);
    transpose_cvt2_kernel<<<dim3(C3_ / 32, C_ / 32, 2), 256>>>(
        w_attn, waT, w_proj, wpT);

    // QKV: q columns pre-scaled by 0.125*log2e in epilogue
    gemm_f16d<true><<<dim3(C3_ / 128, MT_ / 128), 256, 98304>>>(
        xh, waT, b_attn, qkv_h, MT_, C3_, C_);

    attn_f16<<<dim3(TQ_, B_ * H_), 128>>>(qkv_h, att_h);

    // proj
    gemm_f16d<false><<<dim3(C_ / 128, MT_ / 128), 256, 98304>>>(
        att_h, wpT, b_proj, out, MT_, C_, C_);
}